// round 1
// baseline (speedup 1.0000x reference)
#include <cuda_runtime.h>

// ---------------- folded-parameter layout in d_P ----------------
// [0..32)    G      gate weights   [i*8+e]   (4x8)
// [32..40)   gb     gate bias      [e]
// [40..200)  E      per-expert 20: [e*20 + i*4 + j] = EP (4x4), [e*20+16+j] = epb
// [200..216) RP     resid proj     [i*4+j]   (4x4)
// [216..220) rpb
// [220..228) C      comb weights   [i*2+c]   (4x2)
// [228..230) cb
// [230..234) pb     proj bias
#define OFF_G    0
#define OFF_GB   32
#define OFF_E    40
#define OFF_RP   200
#define OFF_RPB  216
#define OFF_C    220
#define OFF_CB   228
#define OFF_PB   230

__device__ float  d_P[256];
__device__ double d_acc[16];   // [0..8): sum of gate probs per expert, [8..16): argmax counts

// ---------------- setup: fold all matrices through w_embed/proj_w ----------------
__global__ __launch_bounds__(512) void setup_kernel(
    const float* __restrict__ w_embed,  const float* __restrict__ b_embed,
    const float* __restrict__ gate_w,   const float* __restrict__ expert_w,
    const float* __restrict__ expert_b, const float* __restrict__ resid_w,
    const float* __restrict__ resid_b,  const float* __restrict__ comb_w,
    const float* __restrict__ comb_b,   const float* __restrict__ proj_w,
    const float* __restrict__ proj_b)
{
    __shared__ float sT[8 * 4 * 16];   // (w_embed @ expert_w[e])[i][k]
    __shared__ float sTb[8 * 16];      // (b_embed @ expert_w[e])[k]
    __shared__ float sR[4 * 16];       // (w_embed @ resid_w)[i][k]
    __shared__ float sRb[16];          // (b_embed @ resid_w)[k] + resid_b

    const int t = threadIdx.x;

    // ---- phase A: sT (all 512 threads) ----
    {
        int e = t >> 6, i = (t >> 4) & 3, k = t & 15;
        float acc = 0.f;
        #pragma unroll
        for (int m = 0; m < 16; m++)
            acc = fmaf(w_embed[i * 16 + m], expert_w[(e * 16 + m) * 16 + k], acc);
        sT[t] = acc;
    }
    // ---- phase B: independent small folds ----
    if (t < 128) {                       // sTb
        int e = t >> 4, k = t & 15;
        float acc = 0.f;
        #pragma unroll
        for (int m = 0; m < 16; m++)
            acc = fmaf(b_embed[m], expert_w[(e * 16 + m) * 16 + k], acc);
        sTb[t] = acc;
    } else if (t < 192) {                // sR
        int u = t - 128, i = u >> 4, k = u & 15;
        float acc = 0.f;
        #pragma unroll
        for (int m = 0; m < 16; m++)
            acc = fmaf(w_embed[i * 16 + m], resid_w[m * 16 + k], acc);
        sR[u] = acc;
    } else if (t < 208) {                // sRb
        int k = t - 192;
        float acc = resid_b[k];
        #pragma unroll
        for (int m = 0; m < 16; m++)
            acc = fmaf(b_embed[m], resid_w[m * 16 + k], acc);
        sRb[k] = acc;
    } else if (t < 240) {                // G
        int u = t - 208, i = u >> 3, e = u & 7;
        float acc = 0.f;
        #pragma unroll
        for (int m = 0; m < 16; m++)
            acc = fmaf(w_embed[i * 16 + m], gate_w[m * 8 + e], acc);
        d_P[OFF_G + i * 8 + e] = acc;
    } else if (t < 248) {                // gb
        int e = t - 240;
        float acc = 0.f;
        #pragma unroll
        for (int m = 0; m < 16; m++)
            acc = fmaf(b_embed[m], gate_w[m * 8 + e], acc);
        d_P[OFF_GB + e] = acc;
    } else if (t < 256) {                // C
        int u = t - 248, i = u >> 1, c = u & 1;
        float acc = 0.f;
        #pragma unroll
        for (int m = 0; m < 16; m++)
            acc = fmaf(w_embed[i * 16 + m], comb_w[m * 2 + c], acc);
        d_P[OFF_C + i * 2 + c] = acc;
    } else if (t < 258) {                // cb
        int c = t - 256;
        float acc = comb_b[c];
        #pragma unroll
        for (int m = 0; m < 16; m++)
            acc = fmaf(b_embed[m], comb_w[m * 2 + c], acc);
        d_P[OFF_CB + c] = acc;
    } else if (t < 262) {                // pb
        d_P[OFF_PB + (t - 258)] = proj_b[t - 258];
    } else if (t < 278) {                // zero accumulators (graph replay!)
        d_acc[t - 262] = 0.0;
    }
    __syncthreads();

    // ---- phase C: multiply the staged folds by proj_w ----
    if (t < 128) {                       // EP[e][i][j]
        int e = t >> 4, i = (t >> 2) & 3, j = t & 3;
        float acc = 0.f;
        #pragma unroll
        for (int k = 0; k < 16; k++)
            acc = fmaf(sT[(e * 4 + i) * 16 + k], proj_w[k * 4 + j], acc);
        d_P[OFF_E + e * 20 + i * 4 + j] = acc;
    } else if (t < 160) {                // epb[e][j]
        int u = t - 128, e = u >> 2, j = u & 3;
        float acc = 0.f;
        #pragma unroll
        for (int k = 0; k < 16; k++)
            acc = fmaf(sTb[e * 16 + k] + expert_b[e * 16 + k], proj_w[k * 4 + j], acc);
        d_P[OFF_E + e * 20 + 16 + j] = acc;
    } else if (t < 176) {                // RP[i][j]
        int u = t - 160, i = u >> 2, j = u & 3;
        float acc = 0.f;
        #pragma unroll
        for (int k = 0; k < 16; k++)
            acc = fmaf(sR[i * 16 + k], proj_w[k * 4 + j], acc);
        d_P[OFF_RP + i * 4 + j] = acc;
    } else if (t < 180) {                // rpb[j]
        int j = t - 176;
        float acc = 0.f;
        #pragma unroll
        for (int k = 0; k < 16; k++)
            acc = fmaf(sRb[k], proj_w[k * 4 + j], acc);
        d_P[OFF_RPB + j] = acc;
    }
}

// ---------------- main per-token kernel ----------------
__global__ __launch_bounds__(256) void moe_main_kernel(
    const float4* __restrict__ x4, float4* __restrict__ o4, int n)
{
    __shared__ float P[256];
    __shared__ float red[8][16];

    const int t = threadIdx.x;
    P[t] = d_P[t];
    __syncthreads();

    float S[8]  = {0.f, 0.f, 0.f, 0.f, 0.f, 0.f, 0.f, 0.f};
    float Cn[8] = {0.f, 0.f, 0.f, 0.f, 0.f, 0.f, 0.f, 0.f};

    const int stride = blockDim.x * gridDim.x;
    for (int i = blockIdx.x * blockDim.x + t; i < n; i += stride) {
        const float4 xv = x4[i];

        // gate logits (folded: x @ G + gb)
        float lg[8];
        #pragma unroll
        for (int e = 0; e < 8; e++)
            lg[e] = fmaf(xv.w, P[24 + e],
                    fmaf(xv.z, P[16 + e],
                    fmaf(xv.y, P[ 8 + e],
                    fmaf(xv.x, P[ 0 + e], P[32 + e]))));

        // argmax (first-max tie break, matching jnp.argmax)
        float m = lg[0]; int idx = 0;
        #pragma unroll
        for (int e = 1; e < 8; e++)
            if (lg[e] > m) { m = lg[e]; idx = e; }

        // softmax probs + per-expert accumulation
        float p[8], sum = 0.f;
        #pragma unroll
        for (int e = 0; e < 8; e++) { p[e] = __expf(lg[e] - m); sum += p[e]; }
        const float inv = __fdividef(1.f, sum);
        #pragma unroll
        for (int e = 0; e < 8; e++) {
            S[e]  += p[e] * inv;
            Cn[e] += (e == idx) ? 1.f : 0.f;
        }
        const float gsel = inv;   // gates[idx] = exp(0)/sum

        // combine weights: softmax over 2 == sigmoid
        const float c0 = fmaf(xv.w, P[226], fmaf(xv.z, P[224], fmaf(xv.y, P[222], fmaf(xv.x, P[220], P[228]))));
        const float c1 = fmaf(xv.w, P[227], fmaf(xv.z, P[225], fmaf(xv.y, P[223], fmaf(xv.x, P[221], P[229]))));
        const float ex  = __expf(c1 - c0);
        const float cw0 = __fdividef(1.f, 1.f + ex);
        const float cw1 = 1.f - cw0;
        const float a   = cw0 * gsel;

        // expert (folded through proj) + residual (folded through proj)
        const int eo = OFF_E + idx * 20;   // stride 20 -> conflict-free shared banks
        float4 o;
        float* op = (float*)&o;
        #pragma unroll
        for (int j = 0; j < 4; j++) {
            float ev = fmaf(xv.w, P[eo + 12 + j],
                       fmaf(xv.z, P[eo +  8 + j],
                       fmaf(xv.y, P[eo +  4 + j],
                       fmaf(xv.x, P[eo +      j], P[eo + 16 + j]))));
            float rv = fmaf(xv.w, P[212 + j],
                       fmaf(xv.z, P[208 + j],
                       fmaf(xv.y, P[204 + j],
                       fmaf(xv.x, P[200 + j], P[216 + j]))));
            op[j] = fmaf(a, ev, fmaf(cw1, rv, P[230 + j]));
        }
        o4[i] = o;
    }

    // ---- aux-loss reduction: warp shuffle -> shared -> global double atomics ----
    #pragma unroll
    for (int e = 0; e < 8; e++) {
        #pragma unroll
        for (int off = 16; off; off >>= 1) {
            S[e]  += __shfl_down_sync(0xffffffffu, S[e],  off);
            Cn[e] += __shfl_down_sync(0xffffffffu, Cn[e], off);
        }
    }
    const int lane = t & 31, w = t >> 5;
    if (lane == 0) {
        #pragma unroll
        for (int e = 0; e < 8; e++) { red[w][e] = S[e]; red[w][8 + e] = Cn[e]; }
    }
    __syncthreads();
    if (t < 16) {
        float v = 0.f;
        #pragma unroll
        for (int w2 = 0; w2 < 8; w2++) v += red[w2][t];
        atomicAdd(&d_acc[t], (double)v);
    }
}

// ---------------- finalize: aux = E * sum_e mean_prob_e * mean_count_e ----------------
__global__ void finalize_kernel(float* __restrict__ out, int n, int out_size)
{
    if (threadIdx.x == 0 && out_size > n * 4) {
        double s = 0.0;
        #pragma unroll
        for (int e = 0; e < 8; e++) s += d_acc[e] * d_acc[8 + e];
        const double dn = (double)n;
        out[n * 4] = (float)(8.0 * s / (dn * dn));
    }
}

extern "C" void kernel_launch(void* const* d_in, const int* in_sizes, int n_in,
                              void* d_out, int out_size)
{
    const float* x        = (const float*)d_in[0];
    const float* w_embed  = (const float*)d_in[1];
    const float* b_embed  = (const float*)d_in[2];
    const float* gate_w   = (const float*)d_in[3];
    const float* expert_w = (const float*)d_in[4];
    const float* expert_b = (const float*)d_in[5];
    const float* resid_w  = (const float*)d_in[6];
    const float* resid_b  = (const float*)d_in[7];
    const float* comb_w   = (const float*)d_in[8];
    const float* comb_b   = (const float*)d_in[9];
    const float* proj_w   = (const float*)d_in[10];
    const float* proj_b   = (const float*)d_in[11];

    const int n = in_sizes[0] / 4;          // number of tokens

    setup_kernel<<<1, 512>>>(w_embed, b_embed, gate_w, expert_w, expert_b,
                             resid_w, resid_b, comb_w, comb_b, proj_w, proj_b);

    int grid = (n + 256 * 8 - 1) / (256 * 8);   // ~8 tokens per thread
    if (grid < 1) grid = 1;
    moe_main_kernel<<<grid, 256>>>((const float4*)x, (float4*)d_out, n);

    finalize_kernel<<<1, 32>>>((float*)d_out, n, out_size);
}